// round 13
// baseline (speedup 1.0000x reference)
#include <cuda_runtime.h>
#include <cstdint>

// ---------------------------------------------------------------------------
// B=8, N=128, S=100, F1=160
// Conv stack per image (1024 images):
//   L1: 1ch 100x100 -> conv3 98 -> pool 49  (10 ch)
//   L2: 10ch 49x49  -> conv3 47 -> pool 23   (WINOGRAD F(2x2,3x3))
//   L3: 10ch 23x23  -> conv3 21 -> pool 10
//   L4: 10ch 10x10  -> conv3 8  -> pool 4   -> 160 features
// ---------------------------------------------------------------------------

#define NIMG 1024

__device__ float g_P1[NIMG * 10 * 49 * 49];
__device__ float g_P2[NIMG * 10 * 23 * 23];
__device__ float g_Hf [NIMG * 160];
__device__ float g_dk1[NIMG * 256];
__device__ float g_dkf[NIMG * 512];
__device__ float g_xx [NIMG];
__device__ float g_XY [8 * 128 * 128];
__device__ float g_avg[NIMG * 160];
__device__ float g_H2 [NIMG * 160];
__device__ float g_H4 [NIMG * 160];
__device__ float g_H6 [NIMG * 160];

// ---------------------------------------------------------------------------
// L1: direct paired conv (FROZEN — Winograd loses at ic=1).
// ---------------------------------------------------------------------------
template<int IC, int IS, int BD>
__global__ __launch_bounds__(BD, 2)
void conv_pool_pair(const float* __restrict__ in,
                    const float* __restrict__ w,
                    const float* __restrict__ bias,
                    float* __restrict__ out)
{
    constexpr int OS = (IS - 2) / 2;
    constexpr int PW = (OS + 1) / 2;
    constexpr int IN = IC * IS * IS;
    constexpr int ITEMS = OS * PW;
    constexpr int WE = 10 * IC * 9;

    extern __shared__ float smem[];
    float* sIn = smem;
    float* sW  = smem + IN;
    float* sB  = sW + WE;

    const int img = blockIdx.x;
    const float* gIn = in + (size_t)img * IN;
    for (int i = threadIdx.x; i < IN; i += BD) sIn[i] = gIn[i];
    for (int i = threadIdx.x; i < WE; i += BD) sW[i] = w[i];
    if (threadIdx.x < 10) sB[threadIdx.x] = bias[threadIdx.x];
    __syncthreads();

    for (int item = threadIdx.x; item < ITEMS; item += BD) {
        const int oy = item / PW;
        const int px = item % PW;
        const int iy0 = 2 * oy;
        const int ix0 = 4 * px;

        #pragma unroll 1
        for (int og = 0; og < 2; ++og) {
            float acc[2][4][5];
            #pragma unroll
            for (int oc = 0; oc < 5; ++oc) {
                const float bv = sB[og * 5 + oc];
                #pragma unroll
                for (int dy = 0; dy < 2; ++dy)
                    #pragma unroll
                    for (int dx = 0; dx < 4; ++dx) acc[dy][dx][oc] = bv;
            }

            #pragma unroll 1
            for (int ic = 0; ic < IC; ++ic) {
                const float* rp = sIn + ic * IS * IS + iy0 * IS + ix0;
                float v[4][6];
                #pragma unroll
                for (int r = 0; r < 4; ++r)
                    #pragma unroll
                    for (int c = 0; c < 6; ++c) v[r][c] = rp[r * IS + c];

                const float* wp = sW + (og * 5) * IC * 9 + ic * 9;
                #pragma unroll
                for (int ky = 0; ky < 3; ++ky)
                    #pragma unroll
                    for (int kx = 0; kx < 3; ++kx)
                        #pragma unroll
                        for (int oc = 0; oc < 5; ++oc) {
                            const float wv = wp[oc * IC * 9 + ky * 3 + kx];
                            #pragma unroll
                            for (int dy = 0; dy < 2; ++dy)
                                #pragma unroll
                                for (int dx = 0; dx < 4; ++dx)
                                    acc[dy][dx][oc] += wv * v[ky + dy][kx + dx];
                        }
            }

            #pragma unroll
            for (int j = 0; j < 2; ++j) {
                const int ox = 2 * px + j;
                if (ox >= OS) break;
                #pragma unroll
                for (int oc = 0; oc < 5; ++oc) {
                    float m = fmaxf(fmaxf(acc[0][2 * j][oc], acc[0][2 * j + 1][oc]),
                                    fmaxf(acc[1][2 * j][oc], acc[1][2 * j + 1][oc]));
                    out[((size_t)img * 10 + og * 5 + oc) * (OS * OS) + oy * OS + ox]
                        = fmaxf(m, 0.0f);
                }
            }
        }
    }
}

// ---------------------------------------------------------------------------
// L2 WINOGRAD F(2x2,3x3): one pooled pixel per thread = one Winograd tile.
// Per (pixel,ic): 16 d-loads, 32 transform adds, 5oc x (4 LDS.128 + 16 FFMA).
// fma-pipe ops 224 vs direct 360 per (pixel,ic) -> 1.6x fewer.
// U = G g G^T precomputed per block into SMEM (coeffs 0.5 exact).
// Bias added after pool-max (uniform -> commutes); relu after.
// ---------------------------------------------------------------------------
__global__ __launch_bounds__(160, 3)
void conv2_wino(const float* __restrict__ in,
                const float* __restrict__ w,
                const float* __restrict__ bias,
                float* __restrict__ out)
{
    constexpr int IC = 10, IS = 49, OS = 23, NR0 = 12;

    const int half = blockIdx.y;
    const int oy0 = half ? NR0 : 0;
    const int nr  = half ? (OS - NR0) : NR0;     // 11 or 12
    const int inRows = 2 * nr + 2;               // 24 or 26

    extern __shared__ float smem[];
    float* sIn = smem;                           // 10 * 26 * 49 = 12740 max
    float* sU  = smem + 10 * 26 * IS;            // 100 pairs x 16 = 1600
    float* sB  = sU + 1600;                      // 10

    const int img = blockIdx.x;
    const int icStride = inRows * IS;
    const float* gIn = in + (size_t)img * IC * IS * IS + (size_t)(2 * oy0) * IS;

    const int total = IC * icStride;
    for (int i = threadIdx.x; i < total; i += 160) {
        const int ic = i / icStride;
        sIn[i] = gIn[ic * IS * IS + (i - ic * icStride)];
    }

    // Weight transform U = G g G^T, one (oc,ic) pair per thread (0..99).
    if (threadIdx.x < 100) {
        const float* gp = w + threadIdx.x * 9;   // pair index = oc*10+ic
        const float g0 = gp[0], g1 = gp[1], g2 = gp[2];
        const float g3 = gp[3], g4 = gp[4], g5 = gp[5];
        const float g6 = gp[6], g7 = gp[7], g8 = gp[8];
        float T[4][3];
        T[0][0] = g0;                    T[0][1] = g1;                    T[0][2] = g2;
        T[1][0] = 0.5f * (g0 + g3 + g6); T[1][1] = 0.5f * (g1 + g4 + g7); T[1][2] = 0.5f * (g2 + g5 + g8);
        T[2][0] = 0.5f * (g0 - g3 + g6); T[2][1] = 0.5f * (g1 - g4 + g7); T[2][2] = 0.5f * (g2 - g5 + g8);
        T[3][0] = g6;                    T[3][1] = g7;                    T[3][2] = g8;
        float* Up = sU + threadIdx.x * 16;
        #pragma unroll
        for (int r = 0; r < 4; ++r) {
            Up[r * 4 + 0] = T[r][0];
            Up[r * 4 + 1] = 0.5f * (T[r][0] + T[r][1] + T[r][2]);
            Up[r * 4 + 2] = 0.5f * (T[r][0] - T[r][1] + T[r][2]);
            Up[r * 4 + 3] = T[r][2];
        }
    }
    if (threadIdx.x < 10) sB[threadIdx.x] = bias[threadIdx.x];
    __syncthreads();

    const int ITEMS = nr * OS;                   // one pooled pixel per item
    for (int item = threadIdx.x; item < ITEMS; item += 160) {
        const int oyr = item / OS;
        const int ox  = item % OS;
        const int iy0 = 2 * oyr;
        const int ix0 = 2 * ox;
        const int oy  = oy0 + oyr;

        #pragma unroll 1
        for (int og = 0; og < 2; ++og) {
            float M[5][16];
            #pragma unroll
            for (int oc = 0; oc < 5; ++oc)
                #pragma unroll
                for (int k = 0; k < 16; ++k) M[oc][k] = 0.0f;

            #pragma unroll 1
            for (int ic = 0; ic < IC; ++ic) {
                const float* rp = sIn + ic * icStride + iy0 * IS + ix0;
                float d[4][4];
                #pragma unroll
                for (int r = 0; r < 4; ++r)
                    #pragma unroll
                    for (int c = 0; c < 4; ++c) d[r][c] = rp[r * IS + c];

                // V = B^T d B
                float t[4][4];
                #pragma unroll
                for (int c = 0; c < 4; ++c) {
                    t[0][c] = d[0][c] - d[2][c];
                    t[1][c] = d[1][c] + d[2][c];
                    t[2][c] = d[2][c] - d[1][c];
                    t[3][c] = d[1][c] - d[3][c];
                }
                float V[16];
                #pragma unroll
                for (int r = 0; r < 4; ++r) {
                    V[r * 4 + 0] = t[r][0] - t[r][2];
                    V[r * 4 + 1] = t[r][1] + t[r][2];
                    V[r * 4 + 2] = t[r][2] - t[r][1];
                    V[r * 4 + 3] = t[r][1] - t[r][3];
                }

                #pragma unroll
                for (int oc = 0; oc < 5; ++oc) {
                    const float4* Up =
                        (const float4*)(sU + ((og * 5 + oc) * 10 + ic) * 16);
                    #pragma unroll
                    for (int q = 0; q < 4; ++q) {
                        const float4 u = Up[q];   // warp-uniform -> broadcast
                        M[oc][q * 4 + 0] += u.x * V[q * 4 + 0];
                        M[oc][q * 4 + 1] += u.y * V[q * 4 + 1];
                        M[oc][q * 4 + 2] += u.z * V[q * 4 + 2];
                        M[oc][q * 4 + 3] += u.w * V[q * 4 + 3];
                    }
                }
            }

            // Y = A^T M A, then pool-max + bias + relu
            #pragma unroll
            for (int oc = 0; oc < 5; ++oc) {
                const float a0 = M[oc][0] + M[oc][4] + M[oc][8];
                const float a1 = M[oc][1] + M[oc][5] + M[oc][9];
                const float a2 = M[oc][2] + M[oc][6] + M[oc][10];
                const float a3 = M[oc][3] + M[oc][7] + M[oc][11];
                const float b0 = M[oc][4] - M[oc][8]  - M[oc][12];
                const float b1 = M[oc][5] - M[oc][9]  - M[oc][13];
                const float b2 = M[oc][6] - M[oc][10] - M[oc][14];
                const float b3 = M[oc][7] - M[oc][11] - M[oc][15];
                const float y00 = a0 + a1 + a2, y01 = a1 - a2 - a3;
                const float y10 = b0 + b1 + b2, y11 = b1 - b2 - b3;
                const float m = fmaxf(fmaxf(y00, y01), fmaxf(y10, y11))
                              + sB[og * 5 + oc];
                out[((size_t)img * 10 + og * 5 + oc) * (OS * OS) + oy * OS + ox]
                    = fmaxf(m, 0.0f);
            }
        }
    }
}

// ---------------------------------------------------------------------------
// Fused L3 + L4 (FROZEN).
// ---------------------------------------------------------------------------
template<int G, int BD>
__global__ __launch_bounds__(BD, 4)
void conv34_fused(const float* __restrict__ in,
                  const float* __restrict__ w3,
                  const float* __restrict__ b3,
                  const float* __restrict__ w4,
                  const float* __restrict__ b4,
                  float* __restrict__ out)
{
    constexpr int IS = 23, OS = 10, PW = 5;
    constexpr int IN = 10 * IS * IS;
    constexpr int MID = 10 * OS * OS;

    extern __shared__ float smem[];
    float* sIn  = smem;
    float* sW3  = sIn + G * IN;
    float* sB3  = sW3 + 900;
    float* sMid = sB3 + 10;
    float* sW4  = sMid + G * MID;
    float* sB4  = sW4 + 900;

    const int img0 = blockIdx.x * G;
    for (int i = threadIdx.x; i < G * IN; i += BD) {
        const int g = i / IN;
        sIn[i] = in[(size_t)(img0 + g) * IN + (i - g * IN)];
    }
    for (int i = threadIdx.x; i < 900; i += BD) { sW3[i] = w3[i]; sW4[i] = w4[i]; }
    if (threadIdx.x < 10) { sB3[threadIdx.x] = b3[threadIdx.x];
                            sB4[threadIdx.x] = b4[threadIdx.x]; }
    __syncthreads();

    for (int item = threadIdx.x; item < G * OS * PW; item += BD) {
        const int g   = item / (OS * PW);
        const int rem = item - g * (OS * PW);
        const int oy  = rem / PW;
        const int px  = rem % PW;
        const int iy0 = 2 * oy, ix0 = 4 * px;
        const float* base = sIn + g * IN;
        float* mid = sMid + g * MID;

        #pragma unroll 1
        for (int og = 0; og < 2; ++og) {
            float acc[2][4][5];
            #pragma unroll
            for (int oc = 0; oc < 5; ++oc) {
                const float bv = sB3[og * 5 + oc];
                #pragma unroll
                for (int dy = 0; dy < 2; ++dy)
                    #pragma unroll
                    for (int dx = 0; dx < 4; ++dx) acc[dy][dx][oc] = bv;
            }

            #pragma unroll 1
            for (int ic = 0; ic < 10; ++ic) {
                const float* rp = base + ic * IS * IS + iy0 * IS + ix0;
                float v[4][6];
                #pragma unroll
                for (int r = 0; r < 4; ++r)
                    #pragma unroll
                    for (int c = 0; c < 6; ++c) v[r][c] = rp[r * IS + c];

                const float* wp = sW3 + (og * 5) * 90 + ic * 9;
                #pragma unroll
                for (int ky = 0; ky < 3; ++ky)
                    #pragma unroll
                    for (int kx = 0; kx < 3; ++kx)
                        #pragma unroll
                        for (int oc = 0; oc < 5; ++oc) {
                            const float wv = wp[oc * 90 + ky * 3 + kx];
                            #pragma unroll
                            for (int dy = 0; dy < 2; ++dy)
                                #pragma unroll
                                for (int dx = 0; dx < 4; ++dx)
                                    acc[dy][dx][oc] += wv * v[ky + dy][kx + dx];
                        }
            }

            #pragma unroll
            for (int j = 0; j < 2; ++j) {
                const int ox = 2 * px + j;
                #pragma unroll
                for (int oc = 0; oc < 5; ++oc) {
                    float m = fmaxf(fmaxf(acc[0][2 * j][oc], acc[0][2 * j + 1][oc]),
                                    fmaxf(acc[1][2 * j][oc], acc[1][2 * j + 1][oc]));
                    mid[(og * 5 + oc) * (OS * OS) + oy * OS + ox] = fmaxf(m, 0.0f);
                }
            }
        }
    }
    __syncthreads();

    for (int item = threadIdx.x; item < G * 16; item += BD) {
        const int g   = item / 16;
        const int pix = item % 16;
        const int oy  = pix / 4, ox = pix % 4;
        const float* mid = sMid + g * MID;

        #pragma unroll 1
        for (int og = 0; og < 2; ++og) {
            float acc[2][2][5];
            #pragma unroll
            for (int oc = 0; oc < 5; ++oc) {
                const float bv = sB4[og * 5 + oc];
                acc[0][0][oc] = bv; acc[0][1][oc] = bv;
                acc[1][0][oc] = bv; acc[1][1][oc] = bv;
            }

            #pragma unroll 1
            for (int ic = 0; ic < 10; ++ic) {
                const float* rp = mid + ic * (OS * OS) + 2 * oy * OS + 2 * ox;
                float v[4][4];
                #pragma unroll
                for (int r = 0; r < 4; ++r)
                    #pragma unroll
                    for (int c = 0; c < 4; ++c) v[r][c] = rp[r * OS + c];

                const float* wp = sW4 + (og * 5) * 90 + ic * 9;
                #pragma unroll
                for (int ky = 0; ky < 3; ++ky)
                    #pragma unroll
                    for (int kx = 0; kx < 3; ++kx)
                        #pragma unroll
                        for (int oc = 0; oc < 5; ++oc) {
                            const float wv = wp[oc * 90 + ky * 3 + kx];
                            #pragma unroll
                            for (int dy = 0; dy < 2; ++dy)
                                #pragma unroll
                                for (int dx = 0; dx < 2; ++dx)
                                    acc[dy][dx][oc] += wv * v[ky + dy][kx + dx];
                        }
            }

            #pragma unroll
            for (int oc = 0; oc < 5; ++oc) {
                float m = fmaxf(fmaxf(acc[0][0][oc], acc[0][1][oc]),
                                fmaxf(acc[1][0][oc], acc[1][1][oc]));
                out[(size_t)(img0 + g) * 160 + (og * 5 + oc) * 16 + pix]
                    = fmaxf(m, 0.0f);
            }
        }
    }
}

// ---------------------------------------------------------------------------
// Double-buffered SGEMM-NT (FROZEN: dense TM=4/BD=128, xy TM=2/BD=256).
// ---------------------------------------------------------------------------
template<int TM, int BD, bool TANH, bool HASBIAS, bool DIAG>
__global__ __launch_bounds__(BD)
void gemmV(const float* __restrict__ A, const float* __restrict__ B,
           const float* __restrict__ bias, float* __restrict__ C,
           float* __restrict__ xxOut,
           int M, int N, int K,
           long long sA, long long sB, long long sC)
{
    constexpr int TN = 2;
    constexpr int TX = 32 / TN;
    constexpr int NLD = 512 / BD;
    __shared__ float As[32][36];
    __shared__ float Bs[32][36];

    const int tid = threadIdx.x;
    const int ty = tid / TX;
    const int tx = tid % TX;

    const int row0 = blockIdx.y * 32;
    const int col0 = blockIdx.x * 32;
    const float* Ab = A + blockIdx.z * sA + (size_t)row0 * K;
    const float* Bb = B + blockIdx.z * sB + (size_t)col0 * K;
    float* Cb = C + blockIdx.z * sC;

    float acc[TM][TN] = {};
    float4 pre[NLD];

    #pragma unroll
    for (int l = 0; l < NLD; ++l) {
        const int i = tid + l * BD;
        const int idx = i & 255;
        const float* src = ((i < 256) ? Ab : Bb)
                         + (size_t)(idx >> 3) * K + (idx & 7) * 4;
        pre[l] = *(const float4*)src;
    }

    for (int k0 = 0; k0 < K; k0 += 32) {
        #pragma unroll
        for (int l = 0; l < NLD; ++l) {
            const int i = tid + l * BD;
            const int idx = i & 255;
            const int r = idx >> 3;
            const int q = idx & 7;
            float* dst = (i < 256) ? &As[q * 4][r] : &Bs[q * 4][r];
            dst[0 * 36] = pre[l].x; dst[1 * 36] = pre[l].y;
            dst[2 * 36] = pre[l].z; dst[3 * 36] = pre[l].w;
        }
        __syncthreads();

        if (k0 + 32 < K) {
            #pragma unroll
            for (int l = 0; l < NLD; ++l) {
                const int i = tid + l * BD;
                const int idx = i & 255;
                const float* src = ((i < 256) ? Ab : Bb)
                                 + (size_t)(idx >> 3) * K + k0 + 32 + (idx & 7) * 4;
                pre[l] = *(const float4*)src;
            }
        }

        #pragma unroll
        for (int kk = 0; kk < 32; ++kk) {
            float a[TM], b[TN];
            if (TM == 4) {
                const float4 t = *(const float4*)&As[kk][ty * 4];
                a[0] = t.x; a[1] = t.y; a[2] = t.z; a[3] = t.w;
            } else {
                const float2 t = *(const float2*)&As[kk][ty * 2];
                a[0] = t.x; a[1] = t.y;
            }
            {
                const float2 t = *(const float2*)&Bs[kk][tx * 2];
                b[0] = t.x; b[1] = t.y;
            }
            #pragma unroll
            for (int i = 0; i < TM; ++i)
                #pragma unroll
                for (int j = 0; j < TN; ++j)
                    acc[i][j] += a[i] * b[j];
        }
        __syncthreads();
    }

    #pragma unroll
    for (int i = 0; i < TM; ++i) {
        const int gr = row0 + ty * TM + i;
        #pragma unroll
        for (int j = 0; j < TN; ++j) {
            const int gc = col0 + tx * TN + j;
            float v = acc[i][j];
            if (HASBIAS) v += bias[gc];
            if (TANH) v = tanhf(v);
            Cb[(size_t)gr * N + gc] = v;
            if (DIAG && gr == gc)
                xxOut[blockIdx.z * 128 + gr] = v;
        }
    }
}

// Fused softmax + message-pass + residual average (FROZEN winner).
__global__ void mix_avg_sm_kernel(const float* __restrict__ xy,
                                  const float* __restrict__ xx,
                                  const float* __restrict__ sigma,
                                  const float* __restrict__ z,
                                  float* __restrict__ out)
{
    const int b  = blockIdx.y;
    const int n0 = blockIdx.x * 8;
    const int t  = threadIdx.x;

    __shared__ float sK[8][128];
    __shared__ float sSum[8];

    const float inv_s = 1.0f / sigma[0];
    const float* xyr = xy + ((size_t)b * 128 + n0) * 128;
    const float* xxb = xx + b * 128;

    for (int i = t; i < 8 * 128; i += 160) {
        const int m = i & 127;
        sK[i >> 7][m] = (2.0f * xyr[i] - xxb[m]) * inv_s;
    }
    __syncthreads();

    if (t < 128) {
        const int r = t >> 4;
        const int s = t & 15;
        float mx = -3.0e38f;
        #pragma unroll
        for (int m = s; m < 128; m += 16) mx = fmaxf(mx, sK[r][m]);
        #pragma unroll
        for (int o = 8; o > 0; o >>= 1)
            mx = fmaxf(mx, __shfl_down_sync(0xFFFFFFFFu, mx, o, 16));
        mx = __shfl_sync(0xFFFFFFFFu, mx, 0, 16);

        float sum = 0.0f;
        #pragma unroll
        for (int m = s; m < 128; m += 16) {
            const float e = expf(sK[r][m] - mx);
            sK[r][m] = e;
            sum += e;
        }
        #pragma unroll
        for (int o = 8; o > 0; o >>= 1)
            sum += __shfl_down_sync(0xFFFFFFFFu, sum, o, 16);
        if (s == 0) sSum[r] = sum;
    }
    __syncthreads();

    if (t < 128) {
        const int r = t >> 4;
        const int s = t & 15;
        const float sum = sSum[r];
        #pragma unroll
        for (int m = s; m < 128; m += 16) sK[r][m] = sK[r][m] / sum;
    }
    __syncthreads();

    const float* zb = z + (size_t)b * 128 * 160;
    float acc[8] = {};
    #pragma unroll 4
    for (int m = 0; m < 128; ++m) {
        const float zv = zb[(size_t)m * 160 + t];
        #pragma unroll
        for (int j = 0; j < 8; ++j) acc[j] += sK[j][m] * zv;
    }
    #pragma unroll
    for (int j = 0; j < 8; ++j)
        out[((size_t)b * 128 + n0 + j) * 160 + t] =
            0.5f * (acc[j] + zb[(size_t)(n0 + j) * 160 + t]);
}

// out[b] = exp( sum_d max_n(H6[b,n,d]) * Wc[d] + bc )
__global__ void final_kernel(const float* __restrict__ H6,
                             const float* __restrict__ Wc,
                             const float* __restrict__ bc,
                             float* __restrict__ out)
{
    const int b = blockIdx.x;
    const int t = threadIdx.x;
    float m = -3.0e38f;
    for (int n = 0; n < 128; ++n)
        m = fmaxf(m, H6[((size_t)b * 128 + n) * 160 + t]);
    float s = m * Wc[t];
    #pragma unroll
    for (int o = 16; o > 0; o >>= 1)
        s += __shfl_down_sync(0xFFFFFFFFu, s, o);
    __shared__ float red[5];
    if ((t & 31) == 0) red[t >> 5] = s;
    __syncthreads();
    if (t == 0) {
        float tot = red[0] + red[1] + red[2] + red[3] + red[4];
        out[b] = expf(tot + bc[0]);
    }
}

// ---------------------------------------------------------------------------
// Host launcher
// ---------------------------------------------------------------------------
extern "C" void kernel_launch(void* const* d_in, const int* in_sizes, int n_in,
                              void* d_out, int out_size)
{
    const float* H     = (const float*)d_in[0];
    const float* w1    = (const float*)d_in[1];
    const float* b1    = (const float*)d_in[2];
    const float* w2    = (const float*)d_in[3];
    const float* b2    = (const float*)d_in[4];
    const float* w3    = (const float*)d_in[5];
    const float* b3    = (const float*)d_in[6];
    const float* w4    = (const float*)d_in[7];
    const float* b4    = (const float*)d_in[8];
    const float* Wdk1  = (const float*)d_in[9];
    const float* bdk1  = (const float*)d_in[10];
    const float* Wdk2  = (const float*)d_in[11];
    const float* bdk2  = (const float*)d_in[12];
    const float* Wt1   = (const float*)d_in[13];
    const float* bt1   = (const float*)d_in[14];
    const float* Wt2   = (const float*)d_in[15];
    const float* bt2   = (const float*)d_in[16];
    const float* Wt3   = (const float*)d_in[17];
    const float* bt3   = (const float*)d_in[18];
    const float* sigma = (const float*)d_in[19];
    const float* Wc    = (const float*)d_in[20];
    const float* bc    = (const float*)d_in[21];

    float *p1, *p2, *hf, *dk1, *dkf, *xx, *xy, *avg, *h2, *h4, *h6;
    cudaGetSymbolAddress((void**)&p1,  g_P1);
    cudaGetSymbolAddress((void**)&p2,  g_P2);
    cudaGetSymbolAddress((void**)&hf,  g_Hf);
    cudaGetSymbolAddress((void**)&dk1, g_dk1);
    cudaGetSymbolAddress((void**)&dkf, g_dkf);
    cudaGetSymbolAddress((void**)&xx,  g_xx);
    cudaGetSymbolAddress((void**)&xy,  g_XY);
    cudaGetSymbolAddress((void**)&avg, g_avg);
    cudaGetSymbolAddress((void**)&h2,  g_H2);
    cudaGetSymbolAddress((void**)&h4,  g_H4);
    cudaGetSymbolAddress((void**)&h6,  g_H6);

    const size_t smem1 = (1 * 100 * 100 + 90 + 10) * sizeof(float);          // 40.4 KB
    const size_t smem2 = (10 * 26 * 49 + 1600 + 10) * sizeof(float);         // 57.4 KB
    const size_t smemf = (2 * 10 * 23 * 23 + 900 + 10 + 2 * 1000 + 900 + 10)
                         * sizeof(float);                                     // 57.6 KB
    cudaFuncSetAttribute(conv2_wino,
                         cudaFuncAttributeMaxDynamicSharedMemorySize, (int)smem2);
    cudaFuncSetAttribute(conv34_fused<2, 128>,
                         cudaFuncAttributeMaxDynamicSharedMemorySize, (int)smemf);

    // ---- Conv stack ----
    conv_pool_pair<1, 100, 256><<<NIMG, 256, smem1>>>(H, w1, b1, p1);
    conv2_wino<<<dim3(NIMG, 2), 160, smem2>>>(p1, w2, b2, p2);
    conv34_fused<2, 128><<<NIMG / 2, 128, smemf>>>(p2, w3, b3, w4, b4, hf);

    // ---- Deep-kernel MLP ----
    gemmV<4, 128, true, true, false><<<dim3(8, 32), 128>>>(
        hf, Wdk1, bdk1, dk1, nullptr, 1024, 256, 160, 0, 0, 0);
    gemmV<4, 128, true, true, false><<<dim3(16, 32), 128>>>(
        dk1, Wdk2, bdk2, dkf, nullptr, 1024, 512, 256, 0, 0, 0);

    // ---- Gram matrix xy (+ diagonal -> xx); softmax fused into mix ----
    gemmV<2, 256, false, false, true><<<dim3(4, 4, 8), 256>>>(
        dkf, dkf, nullptr, xy, xx, 128, 128, 512,
        128LL * 512, 128LL * 512, 128LL * 128);

    dim3 mixg(16, 8);

    // ---- Round 1 ----
    mix_avg_sm_kernel<<<mixg, 160>>>(xy, xx, sigma, hf, avg);
    gemmV<4, 128, true, true, false><<<dim3(5, 32), 128>>>(
        avg, Wt1, bt1, h2, nullptr, 1024, 160, 160, 0, 0, 0);

    // ---- Round 2 ----
    mix_avg_sm_kernel<<<mixg, 160>>>(xy, xx, sigma, h2, avg);
    gemmV<4, 128, true, true, false><<<dim3(5, 32), 128>>>(
        avg, Wt2, bt2, h4, nullptr, 1024, 160, 160, 0, 0, 0);

    // ---- Round 3 ----
    mix_avg_sm_kernel<<<mixg, 160>>>(xy, xx, sigma, h4, avg);
    gemmV<4, 128, true, true, false><<<dim3(5, 32), 128>>>(
        avg, Wt3, bt3, h6, nullptr, 1024, 160, 160, 0, 0, 0);

    // ---- Finish ----
    final_kernel<<<8, 160>>>(h6, Wc, bc, (float*)d_out);
}

// round 14
// speedup vs baseline: 1.0128x; 1.0128x over previous
#include <cuda_runtime.h>
#include <cstdint>

// ---------------------------------------------------------------------------
// B=8, N=128, S=100, F1=160
// Conv stack per image (1024 images):
//   L1: 1ch 100x100 -> conv3 98 -> pool 49  (10 ch)   [2 row-bands/image]
//   L2: 10ch 49x49  -> conv3 47 -> pool 23            [2 row-bands/image]
//   L3: 10ch 23x23  -> conv3 21 -> pool 10  }
//   L4: 10ch 10x10  -> conv3 8  -> pool 4   } fused   -> 160 features
// ---------------------------------------------------------------------------

#define NIMG 1024

__device__ float g_P1[NIMG * 10 * 49 * 49];
__device__ float g_P2[NIMG * 10 * 23 * 23];
__device__ float g_Hf [NIMG * 160];
__device__ float g_dk1[NIMG * 256];
__device__ float g_dkf[NIMG * 512];
__device__ float g_xx [NIMG];
__device__ float g_XY [8 * 128 * 128];
__device__ float g_avg[NIMG * 160];
__device__ float g_H2 [NIMG * 160];
__device__ float g_H4 [NIMG * 160];
__device__ float g_H6 [NIMG * 160];

// ---------------------------------------------------------------------------
// L1: paired conv, 2 row-bands per image (smem 21.2KB, BD=160, 4 blocks/SM).
// Same arithmetic as the monolithic version -> bit-identical output.
// ---------------------------------------------------------------------------
__global__ __launch_bounds__(160, 4)
void conv1_rows(const float* __restrict__ in,
                const float* __restrict__ w,
                const float* __restrict__ bias,
                float* __restrict__ out)
{
    constexpr int IS = 100, OS = 49, PW = 25, NR0 = 25;

    const int half = blockIdx.y;
    const int oy0 = half ? NR0 : 0;
    const int nr  = half ? (OS - NR0) : NR0;     // 24 : 25
    const int inRows = 2 * nr + 2;               // 50 : 52

    extern __shared__ float smem[];
    float* sIn = smem;                           // up to 52*100
    float* sW  = smem + 52 * 100;
    float* sB  = sW + 90;

    const int img = blockIdx.x;
    const float* gIn = in + (size_t)img * IS * IS + (size_t)(2 * oy0) * IS;
    const int total = inRows * IS;
    for (int i = threadIdx.x; i < total; i += 160) sIn[i] = gIn[i];
    for (int i = threadIdx.x; i < 90; i += 160) sW[i] = w[i];
    if (threadIdx.x < 10) sB[threadIdx.x] = bias[threadIdx.x];
    __syncthreads();

    const int ITEMS = nr * PW;
    for (int item = threadIdx.x; item < ITEMS; item += 160) {
        const int oyr = item / PW;
        const int px  = item % PW;
        const int iy0 = 2 * oyr;
        const int ix0 = 4 * px;
        const int oy  = oy0 + oyr;

        #pragma unroll 1
        for (int og = 0; og < 2; ++og) {
            float acc[2][4][5];
            #pragma unroll
            for (int oc = 0; oc < 5; ++oc) {
                const float bv = sB[og * 5 + oc];
                #pragma unroll
                for (int dy = 0; dy < 2; ++dy)
                    #pragma unroll
                    for (int dx = 0; dx < 4; ++dx) acc[dy][dx][oc] = bv;
            }

            const float* rp = sIn + iy0 * IS + ix0;
            float v[4][6];
            #pragma unroll
            for (int r = 0; r < 4; ++r)
                #pragma unroll
                for (int c = 0; c < 6; ++c) v[r][c] = rp[r * IS + c];

            const float* wp = sW + (og * 5) * 9;
            #pragma unroll
            for (int ky = 0; ky < 3; ++ky)
                #pragma unroll
                for (int kx = 0; kx < 3; ++kx)
                    #pragma unroll
                    for (int oc = 0; oc < 5; ++oc) {
                        const float wv = wp[oc * 9 + ky * 3 + kx];
                        #pragma unroll
                        for (int dy = 0; dy < 2; ++dy)
                            #pragma unroll
                            for (int dx = 0; dx < 4; ++dx)
                                acc[dy][dx][oc] += wv * v[ky + dy][kx + dx];
                    }

            #pragma unroll
            for (int j = 0; j < 2; ++j) {
                const int ox = 2 * px + j;
                if (ox >= OS) break;
                #pragma unroll
                for (int oc = 0; oc < 5; ++oc) {
                    float m = fmaxf(fmaxf(acc[0][2 * j][oc], acc[0][2 * j + 1][oc]),
                                    fmaxf(acc[1][2 * j][oc], acc[1][2 * j + 1][oc]));
                    out[((size_t)img * 10 + og * 5 + oc) * (OS * OS) + oy * OS + ox]
                        = fmaxf(m, 0.0f);
                }
            }
        }
    }
}

// ---------------------------------------------------------------------------
// L2: direct paired conv, 2 row-bands (REVERTED to measured-best).
// ---------------------------------------------------------------------------
template<int IC, int IS, int BD>
__global__ __launch_bounds__(BD, 4)
void conv_pool_rows(const float* __restrict__ in,
                    const float* __restrict__ w,
                    const float* __restrict__ bias,
                    float* __restrict__ out)
{
    constexpr int OS = (IS - 2) / 2;    // 23
    constexpr int PW = (OS + 1) / 2;    // 12
    constexpr int WE = 10 * IC * 9;
    constexpr int NR0 = (OS + 1) / 2;   // 12

    const int half = blockIdx.y;
    const int oy0 = half ? NR0 : 0;
    const int nr  = half ? (OS - NR0) : NR0;
    const int inRows = 2 * nr + 2;

    extern __shared__ float smem[];
    float* sIn = smem;
    float* sW  = smem + IC * (2 * NR0 + 2) * IS;
    float* sB  = sW + WE;

    const int img = blockIdx.x;
    const int icStride = inRows * IS;
    const float* gIn = in + (size_t)img * IC * IS * IS + (size_t)(2 * oy0) * IS;

    const int total = IC * icStride;
    for (int i = threadIdx.x; i < total; i += BD) {
        const int ic = i / icStride;
        sIn[i] = gIn[ic * IS * IS + (i - ic * icStride)];
    }
    for (int i = threadIdx.x; i < WE; i += BD) sW[i] = w[i];
    if (threadIdx.x < 10) sB[threadIdx.x] = bias[threadIdx.x];
    __syncthreads();

    const int ITEMS = nr * PW;
    for (int item = threadIdx.x; item < ITEMS; item += BD) {
        const int oyr = item / PW;
        const int px  = item % PW;
        const int iy0 = 2 * oyr;
        const int ix0 = 4 * px;
        const int oy  = oy0 + oyr;

        #pragma unroll 1
        for (int og = 0; og < 2; ++og) {
            float acc[2][4][5];
            #pragma unroll
            for (int oc = 0; oc < 5; ++oc) {
                const float bv = sB[og * 5 + oc];
                #pragma unroll
                for (int dy = 0; dy < 2; ++dy)
                    #pragma unroll
                    for (int dx = 0; dx < 4; ++dx) acc[dy][dx][oc] = bv;
            }

            #pragma unroll 1
            for (int ic = 0; ic < IC; ++ic) {
                const float* rp = sIn + ic * icStride + iy0 * IS + ix0;
                float v[4][6];
                #pragma unroll
                for (int r = 0; r < 4; ++r)
                    #pragma unroll
                    for (int c = 0; c < 6; ++c) v[r][c] = rp[r * IS + c];

                const float* wp = sW + (og * 5) * IC * 9 + ic * 9;
                #pragma unroll
                for (int ky = 0; ky < 3; ++ky)
                    #pragma unroll
                    for (int kx = 0; kx < 3; ++kx)
                        #pragma unroll
                        for (int oc = 0; oc < 5; ++oc) {
                            const float wv = wp[oc * IC * 9 + ky * 3 + kx];
                            #pragma unroll
                            for (int dy = 0; dy < 2; ++dy)
                                #pragma unroll
                                for (int dx = 0; dx < 4; ++dx)
                                    acc[dy][dx][oc] += wv * v[ky + dy][kx + dx];
                        }
            }

            #pragma unroll
            for (int j = 0; j < 2; ++j) {
                const int ox = 2 * px + j;
                if (ox >= OS) break;
                #pragma unroll
                for (int oc = 0; oc < 5; ++oc) {
                    float m = fmaxf(fmaxf(acc[0][2 * j][oc], acc[0][2 * j + 1][oc]),
                                    fmaxf(acc[1][2 * j][oc], acc[1][2 * j + 1][oc]));
                    out[((size_t)img * 10 + og * 5 + oc) * (OS * OS) + oy * OS + ox]
                        = fmaxf(m, 0.0f);
                }
            }
        }
    }
}

// ---------------------------------------------------------------------------
// Fused L3 + L4 (FROZEN measured-best).
// ---------------------------------------------------------------------------
template<int G, int BD>
__global__ __launch_bounds__(BD, 4)
void conv34_fused(const float* __restrict__ in,
                  const float* __restrict__ w3,
                  const float* __restrict__ b3,
                  const float* __restrict__ w4,
                  const float* __restrict__ b4,
                  float* __restrict__ out)
{
    constexpr int IS = 23, OS = 10, PW = 5;
    constexpr int IN = 10 * IS * IS;
    constexpr int MID = 10 * OS * OS;

    extern __shared__ float smem[];
    float* sIn  = smem;
    float* sW3  = sIn + G * IN;
    float* sB3  = sW3 + 900;
    float* sMid = sB3 + 10;
    float* sW4  = sMid + G * MID;
    float* sB4  = sW4 + 900;

    const int img0 = blockIdx.x * G;
    for (int i = threadIdx.x; i < G * IN; i += BD) {
        const int g = i / IN;
        sIn[i] = in[(size_t)(img0 + g) * IN + (i - g * IN)];
    }
    for (int i = threadIdx.x; i < 900; i += BD) { sW3[i] = w3[i]; sW4[i] = w4[i]; }
    if (threadIdx.x < 10) { sB3[threadIdx.x] = b3[threadIdx.x];
                            sB4[threadIdx.x] = b4[threadIdx.x]; }
    __syncthreads();

    for (int item = threadIdx.x; item < G * OS * PW; item += BD) {
        const int g   = item / (OS * PW);
        const int rem = item - g * (OS * PW);
        const int oy  = rem / PW;
        const int px  = rem % PW;
        const int iy0 = 2 * oy, ix0 = 4 * px;
        const float* base = sIn + g * IN;
        float* mid = sMid + g * MID;

        #pragma unroll 1
        for (int og = 0; og < 2; ++og) {
            float acc[2][4][5];
            #pragma unroll
            for (int oc = 0; oc < 5; ++oc) {
                const float bv = sB3[og * 5 + oc];
                #pragma unroll
                for (int dy = 0; dy < 2; ++dy)
                    #pragma unroll
                    for (int dx = 0; dx < 4; ++dx) acc[dy][dx][oc] = bv;
            }

            #pragma unroll 1
            for (int ic = 0; ic < 10; ++ic) {
                const float* rp = base + ic * IS * IS + iy0 * IS + ix0;
                float v[4][6];
                #pragma unroll
                for (int r = 0; r < 4; ++r)
                    #pragma unroll
                    for (int c = 0; c < 6; ++c) v[r][c] = rp[r * IS + c];

                const float* wp = sW3 + (og * 5) * 90 + ic * 9;
                #pragma unroll
                for (int ky = 0; ky < 3; ++ky)
                    #pragma unroll
                    for (int kx = 0; kx < 3; ++kx)
                        #pragma unroll
                        for (int oc = 0; oc < 5; ++oc) {
                            const float wv = wp[oc * 90 + ky * 3 + kx];
                            #pragma unroll
                            for (int dy = 0; dy < 2; ++dy)
                                #pragma unroll
                                for (int dx = 0; dx < 4; ++dx)
                                    acc[dy][dx][oc] += wv * v[ky + dy][kx + dx];
                        }
            }

            #pragma unroll
            for (int j = 0; j < 2; ++j) {
                const int ox = 2 * px + j;
                #pragma unroll
                for (int oc = 0; oc < 5; ++oc) {
                    float m = fmaxf(fmaxf(acc[0][2 * j][oc], acc[0][2 * j + 1][oc]),
                                    fmaxf(acc[1][2 * j][oc], acc[1][2 * j + 1][oc]));
                    mid[(og * 5 + oc) * (OS * OS) + oy * OS + ox] = fmaxf(m, 0.0f);
                }
            }
        }
    }
    __syncthreads();

    for (int item = threadIdx.x; item < G * 16; item += BD) {
        const int g   = item / 16;
        const int pix = item % 16;
        const int oy  = pix / 4, ox = pix % 4;
        const float* mid = sMid + g * MID;

        #pragma unroll 1
        for (int og = 0; og < 2; ++og) {
            float acc[2][2][5];
            #pragma unroll
            for (int oc = 0; oc < 5; ++oc) {
                const float bv = sB4[og * 5 + oc];
                acc[0][0][oc] = bv; acc[0][1][oc] = bv;
                acc[1][0][oc] = bv; acc[1][1][oc] = bv;
            }

            #pragma unroll 1
            for (int ic = 0; ic < 10; ++ic) {
                const float* rp = mid + ic * (OS * OS) + 2 * oy * OS + 2 * ox;
                float v[4][4];
                #pragma unroll
                for (int r = 0; r < 4; ++r)
                    #pragma unroll
                    for (int c = 0; c < 4; ++c) v[r][c] = rp[r * OS + c];

                const float* wp = sW4 + (og * 5) * 90 + ic * 9;
                #pragma unroll
                for (int ky = 0; ky < 3; ++ky)
                    #pragma unroll
                    for (int kx = 0; kx < 3; ++kx)
                        #pragma unroll
                        for (int oc = 0; oc < 5; ++oc) {
                            const float wv = wp[oc * 90 + ky * 3 + kx];
                            #pragma unroll
                            for (int dy = 0; dy < 2; ++dy)
                                #pragma unroll
                                for (int dx = 0; dx < 2; ++dx)
                                    acc[dy][dx][oc] += wv * v[ky + dy][kx + dx];
                        }
            }

            #pragma unroll
            for (int oc = 0; oc < 5; ++oc) {
                float m = fmaxf(fmaxf(acc[0][0][oc], acc[0][1][oc]),
                                fmaxf(acc[1][0][oc], acc[1][1][oc]));
                out[(size_t)(img0 + g) * 160 + (og * 5 + oc) * 16 + pix]
                    = fmaxf(m, 0.0f);
            }
        }
    }
}

// ---------------------------------------------------------------------------
// Double-buffered SGEMM-NT (FROZEN: dense TM=4/BD=128, xy TM=2/BD=256).
// ---------------------------------------------------------------------------
template<int TM, int BD, bool TANH, bool HASBIAS, bool DIAG>
__global__ __launch_bounds__(BD)
void gemmV(const float* __restrict__ A, const float* __restrict__ B,
           const float* __restrict__ bias, float* __restrict__ C,
           float* __restrict__ xxOut,
           int M, int N, int K,
           long long sA, long long sB, long long sC)
{
    constexpr int TN = 2;
    constexpr int TX = 32 / TN;
    constexpr int NLD = 512 / BD;
    __shared__ float As[32][36];
    __shared__ float Bs[32][36];

    const int tid = threadIdx.x;
    const int ty = tid / TX;
    const int tx = tid % TX;

    const int row0 = blockIdx.y * 32;
    const int col0 = blockIdx.x * 32;
    const float* Ab = A + blockIdx.z * sA + (size_t)row0 * K;
    const float* Bb = B + blockIdx.z * sB + (size_t)col0 * K;
    float* Cb = C + blockIdx.z * sC;

    float acc[TM][TN] = {};
    float4 pre[NLD];

    #pragma unroll
    for (int l = 0; l < NLD; ++l) {
        const int i = tid + l * BD;
        const int idx = i & 255;
        const float* src = ((i < 256) ? Ab : Bb)
                         + (size_t)(idx >> 3) * K + (idx & 7) * 4;
        pre[l] = *(const float4*)src;
    }

    for (int k0 = 0; k0 < K; k0 += 32) {
        #pragma unroll
        for (int l = 0; l < NLD; ++l) {
            const int i = tid + l * BD;
            const int idx = i & 255;
            const int r = idx >> 3;
            const int q = idx & 7;
            float* dst = (i < 256) ? &As[q * 4][r] : &Bs[q * 4][r];
            dst[0 * 36] = pre[l].x; dst[1 * 36] = pre[l].y;
            dst[2 * 36] = pre[l].z; dst[3 * 36] = pre[l].w;
        }
        __syncthreads();

        if (k0 + 32 < K) {
            #pragma unroll
            for (int l = 0; l < NLD; ++l) {
                const int i = tid + l * BD;
                const int idx = i & 255;
                const float* src = ((i < 256) ? Ab : Bb)
                                 + (size_t)(idx >> 3) * K + k0 + 32 + (idx & 7) * 4;
                pre[l] = *(const float4*)src;
            }
        }

        #pragma unroll
        for (int kk = 0; kk < 32; ++kk) {
            float a[TM], b[TN];
            if (TM == 4) {
                const float4 t = *(const float4*)&As[kk][ty * 4];
                a[0] = t.x; a[1] = t.y; a[2] = t.z; a[3] = t.w;
            } else {
                const float2 t = *(const float2*)&As[kk][ty * 2];
                a[0] = t.x; a[1] = t.y;
            }
            {
                const float2 t = *(const float2*)&Bs[kk][tx * 2];
                b[0] = t.x; b[1] = t.y;
            }
            #pragma unroll
            for (int i = 0; i < TM; ++i)
                #pragma unroll
                for (int j = 0; j < TN; ++j)
                    acc[i][j] += a[i] * b[j];
        }
        __syncthreads();
    }

    #pragma unroll
    for (int i = 0; i < TM; ++i) {
        const int gr = row0 + ty * TM + i;
        #pragma unroll
        for (int j = 0; j < TN; ++j) {
            const int gc = col0 + tx * TN + j;
            float v = acc[i][j];
            if (HASBIAS) v += bias[gc];
            if (TANH) v = tanhf(v);
            Cb[(size_t)gr * N + gc] = v;
            if (DIAG && gr == gc)
                xxOut[blockIdx.z * 128 + gr] = v;
        }
    }
}

// Fused softmax + message-pass + residual average (FROZEN winner).
__global__ void mix_avg_sm_kernel(const float* __restrict__ xy,
                                  const float* __restrict__ xx,
                                  const float* __restrict__ sigma,
                                  const float* __restrict__ z,
                                  float* __restrict__ out)
{
    const int b  = blockIdx.y;
    const int n0 = blockIdx.x * 8;
    const int t  = threadIdx.x;

    __shared__ float sK[8][128];
    __shared__ float sSum[8];

    const float inv_s = 1.0f / sigma[0];
    const float* xyr = xy + ((size_t)b * 128 + n0) * 128;
    const float* xxb = xx + b * 128;

    for (int i = t; i < 8 * 128; i += 160) {
        const int m = i & 127;
        sK[i >> 7][m] = (2.0f * xyr[i] - xxb[m]) * inv_s;
    }
    __syncthreads();

    if (t < 128) {
        const int r = t >> 4;
        const int s = t & 15;
        float mx = -3.0e38f;
        #pragma unroll
        for (int m = s; m < 128; m += 16) mx = fmaxf(mx, sK[r][m]);
        #pragma unroll
        for (int o = 8; o > 0; o >>= 1)
            mx = fmaxf(mx, __shfl_down_sync(0xFFFFFFFFu, mx, o, 16));
        mx = __shfl_sync(0xFFFFFFFFu, mx, 0, 16);

        float sum = 0.0f;
        #pragma unroll
        for (int m = s; m < 128; m += 16) {
            const float e = expf(sK[r][m] - mx);
            sK[r][m] = e;
            sum += e;
        }
        #pragma unroll
        for (int o = 8; o > 0; o >>= 1)
            sum += __shfl_down_sync(0xFFFFFFFFu, sum, o, 16);
        if (s == 0) sSum[r] = sum;
    }
    __syncthreads();

    if (t < 128) {
        const int r = t >> 4;
        const int s = t & 15;
        const float sum = sSum[r];
        #pragma unroll
        for (int m = s; m < 128; m += 16) sK[r][m] = sK[r][m] / sum;
    }
    __syncthreads();

    const float* zb = z + (size_t)b * 128 * 160;
    float acc[8] = {};
    #pragma unroll 4
    for (int m = 0; m < 128; ++m) {
        const float zv = zb[(size_t)m * 160 + t];
        #pragma unroll
        for (int j = 0; j < 8; ++j) acc[j] += sK[j][m] * zv;
    }
    #pragma unroll
    for (int j = 0; j < 8; ++j)
        out[((size_t)b * 128 + n0 + j) * 160 + t] =
            0.5f * (acc[j] + zb[(size_t)(n0 + j) * 160 + t]);
}

// out[b] = exp( sum_d max_n(H6[b,n,d]) * Wc[d] + bc )
__global__ void final_kernel(const float* __restrict__ H6,
                             const float* __restrict__ Wc,
                             const float* __restrict__ bc,
                             float* __restrict__ out)
{
    const int b = blockIdx.x;
    const int t = threadIdx.x;
    float m = -3.0e38f;
    for (int n = 0; n < 128; ++n)
        m = fmaxf(m, H6[((size_t)b * 128 + n) * 160 + t]);
    float s = m * Wc[t];
    #pragma unroll
    for (int o = 16; o > 0; o >>= 1)
        s += __shfl_down_sync(0xFFFFFFFFu, s, o);
    __shared__ float red[5];
    if ((t & 31) == 0) red[t >> 5] = s;
    __syncthreads();
    if (t == 0) {
        float tot = red[0] + red[1] + red[2] + red[3] + red[4];
        out[b] = expf(tot + bc[0]);
    }
}

// ---------------------------------------------------------------------------
// Host launcher
// ---------------------------------------------------------------------------
extern "C" void kernel_launch(void* const* d_in, const int* in_sizes, int n_in,
                              void* d_out, int out_size)
{
    const float* H     = (const float*)d_in[0];
    const float* w1    = (const float*)d_in[1];
    const float* b1    = (const float*)d_in[2];
    const float* w2    = (const float*)d_in[3];
    const float* b2    = (const float*)d_in[4];
    const float* w3    = (const float*)d_in[5];
    const float* b3    = (const float*)d_in[6];
    const float* w4    = (const float*)d_in[7];
    const float* b4    = (const float*)d_in[8];
    const float* Wdk1  = (const float*)d_in[9];
    const float* bdk1  = (const float*)d_in[10];
    const float* Wdk2  = (const float*)d_in[11];
    const float* bdk2  = (const float*)d_in[12];
    const float* Wt1   = (const float*)d_in[13];
    const float* bt1   = (const float*)d_in[14];
    const float* Wt2   = (const float*)d_in[15];
    const float* bt2   = (const float*)d_in[16];
    const float* Wt3   = (const float*)d_in[17];
    const float* bt3   = (const float*)d_in[18];
    const float* sigma = (const float*)d_in[19];
    const float* Wc    = (const float*)d_in[20];
    const float* bc    = (const float*)d_in[21];

    float *p1, *p2, *hf, *dk1, *dkf, *xx, *xy, *avg, *h2, *h4, *h6;
    cudaGetSymbolAddress((void**)&p1,  g_P1);
    cudaGetSymbolAddress((void**)&p2,  g_P2);
    cudaGetSymbolAddress((void**)&hf,  g_Hf);
    cudaGetSymbolAddress((void**)&dk1, g_dk1);
    cudaGetSymbolAddress((void**)&dkf, g_dkf);
    cudaGetSymbolAddress((void**)&xx,  g_xx);
    cudaGetSymbolAddress((void**)&xy,  g_XY);
    cudaGetSymbolAddress((void**)&avg, g_avg);
    cudaGetSymbolAddress((void**)&h2,  g_H2);
    cudaGetSymbolAddress((void**)&h4,  g_H4);
    cudaGetSymbolAddress((void**)&h6,  g_H6);

    const size_t smem1 = (52 * 100 + 90 + 10) * sizeof(float);               // 21.2 KB
    const size_t smem2 = (10 * 26 * 49 + 900 + 10) * sizeof(float);          // 54.6 KB
    const size_t smemf = (2 * 10 * 23 * 23 + 900 + 10 + 2 * 1000 + 900 + 10)
                         * sizeof(float);                                     // 57.6 KB
    cudaFuncSetAttribute(conv_pool_rows<10, 49, 160>,
                         cudaFuncAttributeMaxDynamicSharedMemorySize, (int)smem2);
    cudaFuncSetAttribute(conv34_fused<2, 128>,
                         cudaFuncAttributeMaxDynamicSharedMemorySize, (int)smemf);

    // ---- Conv stack ----
    conv1_rows<<<dim3(NIMG, 2), 160, smem1>>>(H, w1, b1, p1);
    conv_pool_rows<10, 49, 160><<<dim3(NIMG, 2), 160, smem2>>>(p1, w2, b2, p2);
    conv34_fused<2, 128><<<NIMG / 2, 128, smemf>>>(p2, w3, b3, w4, b4, hf);

    // ---- Deep-kernel MLP ----
    gemmV<4, 128, true, true, false><<<dim3(8, 32), 128>>>(
        hf, Wdk1, bdk1, dk1, nullptr, 1024, 256, 160, 0, 0, 0);
    gemmV<4, 128, true, true, false><<<dim3(16, 32), 128>>>(
        dk1, Wdk2, bdk2, dkf, nullptr, 1024, 512, 256, 0, 0, 0);

    // ---- Gram matrix xy (+ diagonal -> xx); softmax fused into mix ----
    gemmV<2, 256, false, false, true><<<dim3(4, 4, 8), 256>>>(
        dkf, dkf, nullptr, xy, xx, 128, 128, 512,
        128LL * 512, 128LL * 512, 128LL * 128);

    dim3 mixg(16, 8);

    // ---- Round 1 ----
    mix_avg_sm_kernel<<<mixg, 160>>>(xy, xx, sigma, hf, avg);
    gemmV<4, 128, true, true, false><<<dim3(5, 32), 128>>>(
        avg, Wt1, bt1, h2, nullptr, 1024, 160, 160, 0, 0, 0);

    // ---- Round 2 ----
    mix_avg_sm_kernel<<<mixg, 160>>>(xy, xx, sigma, h2, avg);
    gemmV<4, 128, true, true, false><<<dim3(5, 32), 128>>>(
        avg, Wt2, bt2, h4, nullptr, 1024, 160, 160, 0, 0, 0);

    // ---- Round 3 ----
    mix_avg_sm_kernel<<<mixg, 160>>>(xy, xx, sigma, h4, avg);
    gemmV<4, 128, true, true, false><<<dim3(5, 32), 128>>>(
        avg, Wt3, bt3, h6, nullptr, 1024, 160, 160, 0, 0, 0);

    // ---- Finish ----
    final_kernel<<<8, 160>>>(h6, Wc, bc, (float*)d_out);
}